// round 9
// baseline (speedup 1.0000x reference)
#include <cuda_runtime.h>

#define BB 4096
#define TT 512
#define FF 16
#define HH 256
#define OUT_LEN 64
#define ROWS 28
#define GRID 147         // ceil(4096/28)
#define THREADS 512
#define HSU 30           // row stride in u64 units (240B, 16B-aligned, 4-way store conflicts only)

typedef unsigned long long u64;

// -------- packed weight scratch (static device arrays; no allocation) -----
// layout per (k,u): float4 (Wi,Wf,Wg,Wo) == ulonglong2 {(Wi,Wf),(Wg,Wo)} — direct FFMA2 operands.
// padded by 4*HH rows so the k+4..k+7 prefetch at the loop tail stays in-bounds.
__device__ float4 g_encW4[(HH + 4) * HH];
__device__ float4 g_decW4[(HH + 4) * HH];
__device__ float4 g_encX4[FF * HH];
__device__ float4 g_encB4[HH];
__device__ float4 g_decB4[HH];
__device__ float4 g_decX4[HH];

__global__ void pack_weights(const float* __restrict__ encWih, const float* __restrict__ encWhh,
                             const float* __restrict__ encB,   const float* __restrict__ decWih,
                             const float* __restrict__ decWhh, const float* __restrict__ decB)
{
    int idx = blockIdx.x * blockDim.x + threadIdx.x;
    int k = idx >> 8, u = idx & 255;
    if (idx < HH * HH) {
        g_encW4[idx] = make_float4(encWhh[u * HH + k],            encWhh[(HH + u) * HH + k],
                                   encWhh[(2 * HH + u) * HH + k], encWhh[(3 * HH + u) * HH + k]);
        g_decW4[idx] = make_float4(decWhh[u * HH + k],            decWhh[(HH + u) * HH + k],
                                   decWhh[(2 * HH + u) * HH + k], decWhh[(3 * HH + u) * HH + k]);
    }
    if (idx < FF * HH) { // k == f (0..15)
        g_encX4[idx] = make_float4(encWih[u * FF + k],            encWih[(HH + u) * FF + k],
                                   encWih[(2 * HH + u) * FF + k], encWih[(3 * HH + u) * FF + k]);
    }
    if (idx < HH) {
        g_encB4[idx] = make_float4(encB[idx], encB[HH + idx], encB[2 * HH + idx], encB[3 * HH + idx]);
        g_decB4[idx] = make_float4(decB[idx], decB[HH + idx], decB[2 * HH + idx], decB[3 * HH + idx]);
        g_decX4[idx] = make_float4(decWih[idx], decWih[HH + idx], decWih[2 * HH + idx], decWih[3 * HH + idx]);
    }
}

// -------- packed f32x2 helpers --------
__device__ __forceinline__ u64 pack2(float lo, float hi) {
    u64 r; asm("mov.b64 %0, {%1, %2};" : "=l"(r) : "f"(lo), "f"(hi)); return r;
}
__device__ __forceinline__ void fma2(u64& d, u64 a, u64 b) {
    asm("fma.rn.f32x2 %0, %1, %2, %0;" : "+l"(d) : "l"(a), "l"(b));
}
__device__ __forceinline__ float2 unpack2(u64 v) {
    float2 r; asm("mov.b64 {%0, %1}, %2;" : "=f"(r.x), "=f"(r.y) : "l"(v)); return r;
}
__device__ __forceinline__ float tanh_fast(float x) {
    float r; asm("tanh.approx.f32 %0, %1;" : "=f"(r) : "f"(x)); return r;
}
__device__ __forceinline__ float sig_fast(float x) {
    return fmaf(0.5f, tanh_fast(0.5f * x), 0.5f);
}

// dynamic shared memory layout (~67 KB)
struct __align__(16) Smem {
    u64   hd[HH][HSU];     // hd[k][r] = (h_kr, h_kr) duplicated
    u64   xd[FF][HSU];     // xd[f][r] = (x_fr, x_fr) duplicated
    u64   prevd[32];       // decoder prev output, duplicated
    float wout[HH];
    float bout;
};

// One k-step: w = ulonglong2 {(wi,wf),(wg,wo)}; hp_ = 7 broadcast LDS.128 of dup'd values.
#define GATE1(w, hp_)                                                            \
    {                                                                            \
        _Pragma("unroll")                                                        \
        for (int j = 0; j < 7; j++) {                                            \
            ulonglong2 hh = (hp_)[j];                                            \
            fma2(aif[2 * j],     hh.x, (w).x); fma2(ago[2 * j],     hh.x, (w).y);\
            fma2(aif[2 * j + 1], hh.y, (w).x); fma2(ago[2 * j + 1], hh.y, (w).y);\
        }                                                                        \
    }

#define POINTWISE_UPDATE()                                                       \
    _Pragma("unroll")                                                            \
    for (int r = 0; r < 14; r++) {                                               \
        float2 ifv = unpack2(aif[r]);                                            \
        float2 gov = unpack2(ago[r]);                                            \
        float ig = sig_fast(ifv.x), fg = sig_fast(ifv.y);                        \
        float gg = tanh_fast(gov.x), og = sig_fast(gov.y);                       \
        c[r] = fg * c[r] + ig * gg;                                              \
        float hv = og * tanh_fast(c[r]);                                         \
        sm->hd[u][rb + r] = pack2(hv, hv);                                       \
    }

__global__ __launch_bounds__(THREADS, 1)
void lstm_kernel(const float* __restrict__ x, const float* __restrict__ Wout,
                 const float* __restrict__ boutp, float* __restrict__ out)
{
    extern __shared__ char smraw[];
    Smem* sm = (Smem*)smraw;

    const int tid  = threadIdx.x;
    const int u    = tid & 255;          // hidden unit owned by this thread
    const int half = tid >> 8;           // 0: rows 0..13, 1: rows 14..27
    const int rb   = half * 14;          // row base within the 28-row tile
    const int b0   = blockIdx.x * ROWS;  // batch tile base

    if (half == 0) sm->wout[u] = Wout[u];
    if (tid == 0) sm->bout = boutp[0];
#pragma unroll
    for (int r = 0; r < 14; r++) sm->hd[u][rb + r] = 0ull;

    float c[14];
#pragma unroll
    for (int r = 0; r < 14; r++) c[r] = 0.0f;

    const ulonglong2* We = (const ulonglong2*)g_encW4;
    const ulonglong2* Xe = (const ulonglong2*)g_encX4;
    const ulonglong2* Be = (const ulonglong2*)g_encB4;
    const ulonglong2* Wd = (const ulonglong2*)g_decW4;
    const ulonglong2* Bd = (const ulonglong2*)g_decB4;
    const ulonglong2* Xd = (const ulonglong2*)g_decX4;

    u64 aif[14], ago[14];

    // ================= encoder: 512 steps =================
    for (int t = 0; t < TT; t++) {
        // loads independent of SMEM — issue before the barrier to hide latency
        ulonglong2 bv = Be[u];
        ulonglong2 w0 = We[0 * HH + u], w1 = We[1 * HH + u];
        ulonglong2 w2 = We[2 * HH + u], w3 = We[3 * HH + u];

        if (tid < FF * ROWS) {   // stage x_t tile (duplicated)
            int r = tid >> 4, f = tid & 15;
            int b = b0 + r; if (b >= BB) b = BB - 1;   // clamp for partial last tile
            float xv = x[(size_t)b * (TT * FF) + t * FF + f];
            sm->xd[f][r] = pack2(xv, xv);
        }
        __syncthreads();

#pragma unroll
        for (int r = 0; r < 14; r++) { aif[r] = bv.x; ago[r] = bv.y; }

        // x @ Wih^T contribution (K = 16)
#pragma unroll
        for (int f = 0; f < FF; f += 4) {
            ulonglong2 a0 = Xe[(f + 0) * HH + u], a1 = Xe[(f + 1) * HH + u];
            ulonglong2 a2 = Xe[(f + 2) * HH + u], a3 = Xe[(f + 3) * HH + u];
            GATE1(a0, (const ulonglong2*)&sm->xd[f + 0][rb]);
            GATE1(a1, (const ulonglong2*)&sm->xd[f + 1][rb]);
            GATE1(a2, (const ulonglong2*)&sm->xd[f + 2][rb]);
            GATE1(a3, (const ulonglong2*)&sm->xd[f + 3][rb]);
        }

        // h @ Whh^T contribution (K = 256) — hot loop, 4k blocks, 1-block-ahead prefetch
        for (int k = 0; k < HH; k += 4) {
            ulonglong2 c0 = w0, c1 = w1, c2 = w2, c3 = w3;
            w0 = We[(k + 4) * HH + u]; w1 = We[(k + 5) * HH + u];   // padded: in-bounds
            w2 = We[(k + 6) * HH + u]; w3 = We[(k + 7) * HH + u];
            GATE1(c0, (const ulonglong2*)&sm->hd[k + 0][rb]);
            GATE1(c1, (const ulonglong2*)&sm->hd[k + 1][rb]);
            GATE1(c2, (const ulonglong2*)&sm->hd[k + 2][rb]);
            GATE1(c3, (const ulonglong2*)&sm->hd[k + 3][rb]);
        }
        __syncthreads();   // all reads of hd/xd done

        POINTWISE_UPDATE();
        // next iteration's barrier orders these hd writes before reads
    }
    __syncthreads();
    if (tid < 32) sm->prevd[tid] = 0ull;
    __syncthreads();

    // ================= decoder: 64 steps =================
    for (int s = 0; s < OUT_LEN; s++) {
        ulonglong2 bv = Bd[u];
        ulonglong2 dxw = Xd[u];
        ulonglong2 w0 = Wd[0 * HH + u], w1 = Wd[1 * HH + u];
        ulonglong2 w2 = Wd[2 * HH + u], w3 = Wd[3 * HH + u];

#pragma unroll
        for (int r = 0; r < 14; r++) { aif[r] = bv.x; ago[r] = bv.y; }

        // scalar input contribution: prev * dec_Wih
        GATE1(dxw, (const ulonglong2*)&sm->prevd[rb]);

        for (int k = 0; k < HH; k += 4) {
            ulonglong2 c0 = w0, c1 = w1, c2 = w2, c3 = w3;
            w0 = Wd[(k + 4) * HH + u]; w1 = Wd[(k + 5) * HH + u];
            w2 = Wd[(k + 6) * HH + u]; w3 = Wd[(k + 7) * HH + u];
            GATE1(c0, (const ulonglong2*)&sm->hd[k + 0][rb]);
            GATE1(c1, (const ulonglong2*)&sm->hd[k + 1][rb]);
            GATE1(c2, (const ulonglong2*)&sm->hd[k + 2][rb]);
            GATE1(c3, (const ulonglong2*)&sm->hd[k + 3][rb]);
        }
        __syncthreads();   // reads done (prevd + hd)

        POINTWISE_UPDATE();
        __syncthreads();   // hd complete before output reduction

        // output head: 16 warps reduce 28 rows (warp w: row w, and row 16+w for w<12)
        {
            int warp = tid >> 5, lane = tid & 31;
#pragma unroll
            for (int j = 0; j < 2; j++) {
                int r = warp + 16 * j;
                if (r < ROWS) {
                    float p = 0.0f;
#pragma unroll
                    for (int i = 0; i < 8; i++) {
                        int kk = lane + 32 * i;
                        p += *(const float*)&sm->hd[kk][r] * sm->wout[kk];
                    }
#pragma unroll
                    for (int off = 16; off; off >>= 1) p += __shfl_xor_sync(0xffffffffu, p, off);
                    if (lane == 0) {
                        float val = p + sm->bout;
                        if (b0 + r < BB) out[(size_t)(b0 + r) * OUT_LEN + s] = val;
                        sm->prevd[r] = pack2(val, val);
                    }
                }
            }
        }
        __syncthreads();   // prevd/hd stable before next step
    }
}

extern "C" void kernel_launch(void* const* d_in, const int* in_sizes, int n_in,
                              void* d_out, int out_size)
{
    const float* x      = (const float*)d_in[0];
    const float* encWih = (const float*)d_in[1];
    const float* encWhh = (const float*)d_in[2];
    const float* encB   = (const float*)d_in[3];
    const float* decWih = (const float*)d_in[4];
    const float* decWhh = (const float*)d_in[5];
    const float* decB   = (const float*)d_in[6];
    const float* Wout   = (const float*)d_in[7];
    const float* bout   = (const float*)d_in[8];
    float* out = (float*)d_out;

    pack_weights<<<(HH * HH + 255) / 256, 256>>>(encWih, encWhh, encB, decWih, decWhh, decB);

    // dynamic smem > 48KB opt-in (host attribute set; idempotent, capture-safe)
    static int smem_set = 0;
    if (!smem_set) {
        cudaFuncSetAttribute(lstm_kernel, cudaFuncAttributeMaxDynamicSharedMemorySize,
                             (int)sizeof(Smem));
        smem_set = 1;
    }
    lstm_kernel<<<GRID, THREADS, sizeof(Smem)>>>(x, Wout, bout, out);
}